// round 1
// baseline (speedup 1.0000x reference)
#include <cuda_runtime.h>

#define FULL 0xffffffffu

static constexpr int Tt  = 16;
static constexpr int HWc = 4096;
static constexpr int NMAX = 4 * 16 * 4096;   // 262144 nodes

// Scratch (allocation-free: device globals)
__device__ float        g_S[(size_t)NMAX * 64];  // 64 MB edge-sum accumulator
__device__ float        g_s0[NMAX];              // sum of edge weights per node
__device__ unsigned char g_mask[NMAX];           // node received >=1 edge

// ---------------------------------------------------------------------------
// Zero scratch (must run every launch; graph replays reuse the globals)
// ---------------------------------------------------------------------------
__global__ void __launch_bounds__(256) zero_kernel(int N) {
    const int stride = gridDim.x * blockDim.x;
    const int i = blockIdx.x * blockDim.x + threadIdx.x;
    const float4 z = make_float4(0.f, 0.f, 0.f, 0.f);
    const size_t total4 = (size_t)N * 16;   // N*64 floats as float4
    for (size_t j = i; j < total4; j += stride)
        reinterpret_cast<float4*>(g_S)[j] = z;
    for (int j = i; j < N; j += stride) {
        g_s0[j] = 0.f;
        g_mask[j] = 0;
    }
}

// ---------------------------------------------------------------------------
// Edge kernel: one warp per edge.
//   pd  = position[t+1, ed] - position[t, es]            (2)
//   h   = leaky_relu(pd @ W1 + b1)                        (64)
//   de  = GroupNorm(h @ W2 + b2; gn_d)                    (64)
//   scatter: S[suc] += w * (gf[pre] + de); s0[suc] += w; mask[suc] = 1
// ---------------------------------------------------------------------------
__global__ void __launch_bounds__(256) edge_kernel(
    const float* __restrict__ gf,
    const float* __restrict__ pos,
    const int*   __restrict__ edge,
    const float* __restrict__ wgt,
    const float* __restrict__ W1,
    const float* __restrict__ b1,
    const float* __restrict__ W2,
    const float* __restrict__ b2,
    const float* __restrict__ gdg,
    const float* __restrict__ gdb,
    int E)
{
    __shared__ float sW2[64 * 64];
    __shared__ float sW1[128];
    __shared__ float sb1[64], sb2[64], sg[64], sbt[64];

    for (int i = threadIdx.x; i < 64 * 64; i += 256) sW2[i] = W2[i];
    if (threadIdx.x < 128) sW1[threadIdx.x] = W1[threadIdx.x];
    if (threadIdx.x < 64) {
        sb1[threadIdx.x] = b1[threadIdx.x];
        sb2[threadIdx.x] = b2[threadIdx.x];
        sg[threadIdx.x]  = gdg[threadIdx.x];
        sbt[threadIdx.x] = gdb[threadIdx.x];
    }
    __syncthreads();

    const int lane = threadIdx.x & 31;
    const int warp = threadIdx.x >> 5;
    const int c0   = lane * 2;          // this lane owns channels c0, c0+1
    const int stride = gridDim.x * 8;

    for (int e = blockIdx.x * 8 + warp; e < E; e += stride) {
        const int4 ed = __ldg(reinterpret_cast<const int4*>(edge) + e);
        // ed.x=eb, ed.y=et, ed.z=es, ed.w=ed(dst)
        const int base = (ed.x * Tt + ed.y) * HWc;
        const int pre  = base + ed.z;
        const int suc  = base + HWc + ed.w;

        const float2 P0 = __ldg(reinterpret_cast<const float2*>(pos) + ed.y * HWc + ed.z);
        const float2 P1 = __ldg(reinterpret_cast<const float2*>(pos) + (ed.y + 1) * HWc + ed.w);
        const float pd0 = P1.x - P0.x;
        const float pd1 = P1.y - P0.y;

        // h[k] for k = lane and k = lane+32
        const int k2 = lane + 32;
        float za = fmaf(pd1, sW1[64 + lane], fmaf(pd0, sW1[lane], sb1[lane]));
        float zb = fmaf(pd1, sW1[64 + k2],   fmaf(pd0, sW1[k2],   sb1[k2]));
        const float ha = za > 0.f ? za : 0.01f * za;
        const float hb = zb > 0.f ? zb : 0.01f * zb;

        // y = h @ W2 + b2 ; lane accumulates channels c0, c0+1
        float2 acc;
        acc.x = sb2[c0];
        acc.y = sb2[c0 + 1];
        #pragma unroll
        for (int k = 0; k < 32; k++) {
            const float hk = __shfl_sync(FULL, ha, k);
            const float2 wv = *reinterpret_cast<const float2*>(sW2 + k * 64 + c0);
            acc.x = fmaf(hk, wv.x, acc.x);
            acc.y = fmaf(hk, wv.y, acc.y);
        }
        #pragma unroll
        for (int k = 0; k < 32; k++) {
            const float hk = __shfl_sync(FULL, hb, k);
            const float2 wv = *reinterpret_cast<const float2*>(sW2 + (k + 32) * 64 + c0);
            acc.x = fmaf(hk, wv.x, acc.x);
            acc.y = fmaf(hk, wv.y, acc.y);
        }

        // GroupNorm over 64 channels (warp reduction)
        float s = acc.x + acc.y;
        float q = fmaf(acc.x, acc.x, acc.y * acc.y);
        #pragma unroll
        for (int o = 16; o > 0; o >>= 1) {
            s += __shfl_xor_sync(FULL, s, o);
            q += __shfl_xor_sync(FULL, q, o);
        }
        const float mean = s * 0.015625f;
        const float var  = q * 0.015625f - mean * mean;
        const float rs   = rsqrtf(var + 1e-5f);
        const float dx = (acc.x - mean) * rs * sg[c0]     + sbt[c0];
        const float dy = (acc.y - mean) * rs * sg[c0 + 1] + sbt[c0 + 1];

        const float  w = __ldg(wgt + e);
        const float2 v = __ldg(reinterpret_cast<const float2*>(gf) + pre * 32 + lane);
        const float ox = w * (v.x + dx);
        const float oy = w * (v.y + dy);

        // pair up adjacent lanes -> one 16B reduction per 4 channels
        const float px = __shfl_down_sync(FULL, ox, 1);
        const float py = __shfl_down_sync(FULL, oy, 1);
        if ((lane & 1) == 0) {
            float* addr = g_S + (size_t)suc * 64 + c0;
            asm volatile("red.global.add.v4.f32 [%0], {%1, %2, %3, %4};"
                         :: "l"(addr), "f"(ox), "f"(oy), "f"(px), "f"(py)
                         : "memory");
        }
        if (lane == 0) {
            atomicAdd(g_s0 + suc, w);
            g_mask[suc] = 1;
        }
    }
}

// ---------------------------------------------------------------------------
// Node kernel: one warp per node.
//   copy = GN(S @ Wa + s0*ba; gn_n)
//   out  = mask ? leaky_relu(GN([gf, copy] @ Wf + bf; gn_f)) : gf
// ---------------------------------------------------------------------------
__global__ void __launch_bounds__(256) node_kernel(
    const float* __restrict__ gf,
    const float* __restrict__ Wa,
    const float* __restrict__ ba,
    const float* __restrict__ gng,
    const float* __restrict__ gnb,
    const float* __restrict__ Wf,
    const float* __restrict__ bf,
    const float* __restrict__ gfg,
    const float* __restrict__ gfb,
    float* __restrict__ out,
    int N)
{
    __shared__ float sWa[64 * 64];     // 16 KB
    __shared__ float sWf[128 * 64];    // 32 KB  (total exactly 48 KB static)
    for (int i = threadIdx.x; i < 64 * 64; i += 256)  sWa[i] = Wa[i];
    for (int i = threadIdx.x; i < 128 * 64; i += 256) sWf[i] = Wf[i];
    __syncthreads();

    const int lane = threadIdx.x & 31;
    const int warp = threadIdx.x >> 5;
    const int c0   = lane * 2;
    const int stride = gridDim.x * 8;

    for (int n = blockIdx.x * 8 + warp; n < N; n += stride) {
        const float2 g = __ldg(reinterpret_cast<const float2*>(gf) + n * 32 + lane);
        float2* outp = reinterpret_cast<float2*>(out) + n * 32 + lane;
        if (!g_mask[n]) {                 // warp-uniform branch
            *outp = g;
            continue;
        }
        const float2 Sv = *(reinterpret_cast<const float2*>(g_S) + (size_t)n * 32 + lane);
        const float  s0 = g_s0[n];

        // copy_pre = S @ Wa + s0 * ba
        float2 acc;
        acc.x = s0 * __ldg(ba + c0);
        acc.y = s0 * __ldg(ba + c0 + 1);
        #pragma unroll
        for (int kk = 0; kk < 32; kk++) {
            const float k0 = __shfl_sync(FULL, Sv.x, kk);
            const float k1 = __shfl_sync(FULL, Sv.y, kk);
            const float2 w0 = *reinterpret_cast<const float2*>(sWa + (2 * kk) * 64 + c0);
            const float2 w1 = *reinterpret_cast<const float2*>(sWa + (2 * kk + 1) * 64 + c0);
            acc.x = fmaf(k0, w0.x, acc.x); acc.y = fmaf(k0, w0.y, acc.y);
            acc.x = fmaf(k1, w1.x, acc.x); acc.y = fmaf(k1, w1.y, acc.y);
        }

        // GroupNorm (gn_n)
        float s = acc.x + acc.y;
        float q = fmaf(acc.x, acc.x, acc.y * acc.y);
        #pragma unroll
        for (int o = 16; o > 0; o >>= 1) {
            s += __shfl_xor_sync(FULL, s, o);
            q += __shfl_xor_sync(FULL, q, o);
        }
        float mean = s * 0.015625f;
        float var  = q * 0.015625f - mean * mean;
        float rs   = rsqrtf(var + 1e-5f);
        float2 cp;
        cp.x = (acc.x - mean) * rs * __ldg(gng + c0)     + __ldg(gnb + c0);
        cp.y = (acc.y - mean) * rs * __ldg(gng + c0 + 1) + __ldg(gnb + c0 + 1);

        // fused = [gf, copy] @ Wf + bf
        float2 a2;
        a2.x = __ldg(bf + c0);
        a2.y = __ldg(bf + c0 + 1);
        #pragma unroll
        for (int kk = 0; kk < 32; kk++) {
            const float k0 = __shfl_sync(FULL, g.x, kk);
            const float k1 = __shfl_sync(FULL, g.y, kk);
            const float2 w0 = *reinterpret_cast<const float2*>(sWf + (2 * kk) * 64 + c0);
            const float2 w1 = *reinterpret_cast<const float2*>(sWf + (2 * kk + 1) * 64 + c0);
            a2.x = fmaf(k0, w0.x, a2.x); a2.y = fmaf(k0, w0.y, a2.y);
            a2.x = fmaf(k1, w1.x, a2.x); a2.y = fmaf(k1, w1.y, a2.y);
        }
        #pragma unroll
        for (int kk = 0; kk < 32; kk++) {
            const float k0 = __shfl_sync(FULL, cp.x, kk);
            const float k1 = __shfl_sync(FULL, cp.y, kk);
            const float2 w0 = *reinterpret_cast<const float2*>(sWf + (64 + 2 * kk) * 64 + c0);
            const float2 w1 = *reinterpret_cast<const float2*>(sWf + (64 + 2 * kk + 1) * 64 + c0);
            a2.x = fmaf(k0, w0.x, a2.x); a2.y = fmaf(k0, w0.y, a2.y);
            a2.x = fmaf(k1, w1.x, a2.x); a2.y = fmaf(k1, w1.y, a2.y);
        }

        // GroupNorm (gn_f) + leaky_relu
        s = a2.x + a2.y;
        q = fmaf(a2.x, a2.x, a2.y * a2.y);
        #pragma unroll
        for (int o = 16; o > 0; o >>= 1) {
            s += __shfl_xor_sync(FULL, s, o);
            q += __shfl_xor_sync(FULL, q, o);
        }
        mean = s * 0.015625f;
        var  = q * 0.015625f - mean * mean;
        rs   = rsqrtf(var + 1e-5f);
        float fx = (a2.x - mean) * rs * __ldg(gfg + c0)     + __ldg(gfb + c0);
        float fy = (a2.y - mean) * rs * __ldg(gfg + c0 + 1) + __ldg(gfb + c0 + 1);
        fx = fx > 0.f ? fx : 0.01f * fx;
        fy = fy > 0.f ? fy : 0.01f * fy;
        float2 r; r.x = fx; r.y = fy;
        *outp = r;
    }
}

// ---------------------------------------------------------------------------
extern "C" void kernel_launch(void* const* d_in, const int* in_sizes, int n_in,
                              void* d_out, int out_size)
{
    const float* gf  = (const float*)d_in[0];
    const float* pos = (const float*)d_in[1];
    const int*   edg = (const int*)  d_in[2];
    const float* wgt = (const float*)d_in[3];
    const float* W1  = (const float*)d_in[4];
    const float* b1  = (const float*)d_in[5];
    const float* W2  = (const float*)d_in[6];
    const float* b2  = (const float*)d_in[7];
    const float* gdg = (const float*)d_in[8];
    const float* gdb = (const float*)d_in[9];
    const float* Wa  = (const float*)d_in[10];
    const float* ba  = (const float*)d_in[11];
    const float* gng = (const float*)d_in[12];
    const float* gnb = (const float*)d_in[13];
    const float* Wf  = (const float*)d_in[14];
    const float* bf  = (const float*)d_in[15];
    const float* gfg = (const float*)d_in[16];
    const float* gfb = (const float*)d_in[17];
    float* out = (float*)d_out;

    const int E = in_sizes[3];        // weight count = #edges
    const int N = in_sizes[0] / 64;   // nodes

    zero_kernel<<<1024, 256>>>(N);
    edge_kernel<<<1184, 256>>>(gf, pos, edg, wgt, W1, b1, W2, b2, gdg, gdb, E);
    node_kernel<<<592, 256>>>(gf, Wa, ba, gng, gnb, Wf, bf, gfg, gfb, out, N);
}

// round 3
// speedup vs baseline: 2.2394x; 2.2394x over previous
#include <cuda_runtime.h>

#define FULL 0xffffffffu

static constexpr int NMAX = 262144;   // 4*16*4096 nodes

// Scratch (allocation-free: device globals)
__device__ float         g_S[(size_t)NMAX * 64];
__device__ float         g_s0[NMAX];
__device__ unsigned char g_mask[NMAX];

// ---------------------------------------------------------------------------
// butterfly reduction of two values across the warp
__device__ __forceinline__ void warp_reduce2(float& s, float& q) {
    #pragma unroll
    for (int o = 16; o > 0; o >>= 1) {
        s += __shfl_xor_sync(FULL, s, o);
        q += __shfl_xor_sync(FULL, q, o);
    }
}

// packed f32x2 FMA: acc += {ax,ay} * {bx,by}
__device__ __forceinline__ void ffma2(float2& acc, float ax, float ay,
                                      float bx, float by) {
    float2 a = make_float2(ax, ay);
    float2 b = make_float2(bx, by);
    asm("fma.rn.f32x2 %0, %1, %2, %0;"
        : "+l"(reinterpret_cast<unsigned long long&>(acc))
        : "l"(reinterpret_cast<unsigned long long&>(a)),
          "l"(reinterpret_cast<unsigned long long&>(b)));
}

// ---------------------------------------------------------------------------
__global__ void __launch_bounds__(256) zero_kernel(int N) {
    const int stride = gridDim.x * blockDim.x;
    const int i = blockIdx.x * blockDim.x + threadIdx.x;
    const float4 z = make_float4(0.f, 0.f, 0.f, 0.f);
    const size_t total4 = (size_t)N * 16;
    for (size_t j = i; j < total4; j += stride)
        reinterpret_cast<float4*>(g_S)[j] = z;
    for (int j = i; j < N; j += stride) {
        g_s0[j] = 0.f;
        g_mask[j] = 0;
    }
}

// ---------------------------------------------------------------------------
// Edge kernel: warp processes 4 edges per iteration.
// Transposed W2 in smem (pitch 68), h staged in smem, f32x2 FMAs.
// ---------------------------------------------------------------------------
__global__ void __launch_bounds__(256, 3) edge_kernel(
    const float* __restrict__ gf,
    const float* __restrict__ pos,
    const int*   __restrict__ edge,
    const float* __restrict__ wgt,
    const float* __restrict__ W1,
    const float* __restrict__ b1,
    const float* __restrict__ W2,
    const float* __restrict__ b2,
    const float* __restrict__ gdg,
    const float* __restrict__ gdb,
    int E)
{
    __shared__ float sW2t[64 * 68];     // W2t[c][k] = W2[k][c], pitch 68
    __shared__ float sht[8 * 4 * 64];   // h staging: [warp][edge][k]

    for (int i = threadIdx.x; i < 64 * 64; i += 256) {
        int k = i >> 6, c = i & 63;
        sW2t[c * 68 + k] = W2[i];
    }
    __syncthreads();

    const int lane = threadIdx.x & 31;
    const int warp = threadIdx.x >> 5;
    const int lhi  = lane + 32;

    // per-lane constants in registers (channels lane, lane+32)
    const float w1aLo = __ldg(W1 + lane),     w1bLo = __ldg(W1 + 64 + lane);
    const float w1aHi = __ldg(W1 + lhi),      w1bHi = __ldg(W1 + 64 + lhi);
    const float b1Lo  = __ldg(b1 + lane),     b1Hi  = __ldg(b1 + lhi);
    const float b2Lo  = __ldg(b2 + lane),     b2Hi  = __ldg(b2 + lhi);
    const float gLo   = __ldg(gdg + lane),    gHi   = __ldg(gdg + lhi);
    const float btLo  = __ldg(gdb + lane),    btHi  = __ldg(gdb + lhi);

    float* hme = sht + warp * 256;
    const float4* wrLo = reinterpret_cast<const float4*>(sW2t + lane * 68);
    const float4* wrHi = reinterpret_cast<const float4*>(sW2t + lhi * 68);

    const int nw = gridDim.x * 8;
    for (int e0 = (blockIdx.x * 8 + warp) * 4; e0 < E; e0 += nw * 4) {
        int pre = 0, suc = 0;
        float pd0 = 0.f, pd1 = 0.f, w = 0.f;
        if (lane < 4) {
            const int ei = min(e0 + lane, E - 1);
            const int4 ed = __ldg(reinterpret_cast<const int4*>(edge) + ei);
            pre = (ed.x * 16 + ed.y) * 4096 + ed.z;
            suc = pre - ed.z + 4096 + ed.w;
            const float2 P0 = __ldg(reinterpret_cast<const float2*>(pos) + ed.y * 4096 + ed.z);
            const float2 P1 = __ldg(reinterpret_cast<const float2*>(pos) + (ed.y + 1) * 4096 + ed.w);
            pd0 = P1.x - P0.x;
            pd1 = P1.y - P0.y;
            w = __ldg(wgt + ei);
        }
        __syncwarp();
        // compute + stage h for 4 edges (natural k order)
        #pragma unroll
        for (int e = 0; e < 4; e++) {
            const float p0 = __shfl_sync(FULL, pd0, e);
            const float p1 = __shfl_sync(FULL, pd1, e);
            const float za = fmaf(p1, w1bLo, fmaf(p0, w1aLo, b1Lo));
            const float zb = fmaf(p1, w1bHi, fmaf(p0, w1aHi, b1Hi));
            hme[e * 64 + lane] = za > 0.f ? za : 0.01f * za;
            hme[e * 64 + lhi]  = zb > 0.f ? zb : 0.01f * zb;
        }
        __syncwarp();

        float2 aLo[4], aHi[4];
        #pragma unroll
        for (int e = 0; e < 4; e++) {
            aLo[e] = make_float2(b2Lo, 0.f);
            aHi[e] = make_float2(b2Hi, 0.f);
        }
        #pragma unroll
        for (int kq = 0; kq < 16; kq++) {
            const float4 wl = wrLo[kq];
            const float4 wh = wrHi[kq];
            #pragma unroll
            for (int e = 0; e < 4; e++) {
                const float4 h4 = *reinterpret_cast<const float4*>(hme + e * 64 + kq * 4);
                ffma2(aLo[e], h4.x, h4.y, wl.x, wl.y);
                ffma2(aLo[e], h4.z, h4.w, wl.z, wl.w);
                ffma2(aHi[e], h4.x, h4.y, wh.x, wh.y);
                ffma2(aHi[e], h4.z, h4.w, wh.z, wh.w);
            }
        }

        #pragma unroll
        for (int e = 0; e < 4; e++) {
            const float yLo = aLo[e].x + aLo[e].y;
            const float yHi = aHi[e].x + aHi[e].y;
            float s = yLo + yHi;
            float q = fmaf(yLo, yLo, yHi * yHi);
            warp_reduce2(s, q);
            const float mean = s * 0.015625f;
            const float var  = fmaf(q, 0.015625f, -mean * mean);
            const float rs   = rsqrtf(var + 1e-5f);
            const float dLo = fmaf((yLo - mean) * rs, gLo, btLo);
            const float dHi = fmaf((yHi - mean) * rs, gHi, btHi);

            const int   preE = __shfl_sync(FULL, pre, e);
            const int   sucE = __shfl_sync(FULL, suc, e);
            const float wE   = __shfl_sync(FULL, w, e);

            const float vLo = __ldg(gf + (size_t)preE * 64 + lane);
            const float vHi = __ldg(gf + (size_t)preE * 64 + lhi);
            const float ox = wE * (vLo + dLo);
            const float oy = wE * (vHi + dHi);

            // regroup for vectorized reductions
            const float a1 = __shfl_down_sync(FULL, ox, 1);
            const float a2 = __shfl_down_sync(FULL, ox, 2);
            const float a3 = __shfl_down_sync(FULL, ox, 3);
            const float u2 = __shfl_up_sync(FULL, oy, 2);
            const float u1 = __shfl_up_sync(FULL, oy, 1);
            const float d1 = __shfl_down_sync(FULL, oy, 1);

            if (e0 + e < E) {
                if ((lane & 3) == 0) {
                    float* adr = g_S + (size_t)sucE * 64 + lane;   // channels lane..lane+3
                    asm volatile("red.global.add.v4.f32 [%0], {%1,%2,%3,%4};"
                                 :: "l"(adr), "f"(ox), "f"(a1), "f"(a2), "f"(a3) : "memory");
                }
                if ((lane & 3) == 2) {
                    float* adr = g_S + (size_t)sucE * 64 + 30 + lane; // channels 32+(lane-2)..
                    asm volatile("red.global.add.v4.f32 [%0], {%1,%2,%3,%4};"
                                 :: "l"(adr), "f"(u2), "f"(u1), "f"(oy), "f"(d1) : "memory");
                }
                if (lane == 0) {
                    atomicAdd(g_s0 + sucE, wE);
                    g_mask[sucE] = 1;
                }
            }
        }
    }
}

// ---------------------------------------------------------------------------
// Node kernel: warp processes 4 nodes per iteration. Dynamic smem:
// Wa^T (pitch 68) + Wf^T (pitch 132) + activation staging [warp][node][128].
// ---------------------------------------------------------------------------
__global__ void __launch_bounds__(256, 3) node_kernel(
    const float* __restrict__ gf,
    const float* __restrict__ Wa,
    const float* __restrict__ ba,
    const float* __restrict__ gng,
    const float* __restrict__ gnb,
    const float* __restrict__ Wf,
    const float* __restrict__ bf,
    const float* __restrict__ gfg,
    const float* __restrict__ gfb,
    float* __restrict__ out,
    int N)
{
    extern __shared__ float sm[];
    float* sWa  = sm;                    // 64*68  = 4352 floats
    float* sWf  = sm + 4352;             // 64*132 = 8448 floats
    float* sAct = sm + 4352 + 8448;      // 8*4*128 = 4096 floats

    for (int i = threadIdx.x; i < 64 * 64; i += 256) {
        int k = i >> 6, c = i & 63;
        sWa[c * 68 + k] = Wa[i];
    }
    for (int i = threadIdx.x; i < 128 * 64; i += 256) {
        int k = i >> 6, c = i & 63;
        sWf[c * 132 + k] = Wf[i];
    }
    __syncthreads();

    const int lane = threadIdx.x & 31;
    const int warp = threadIdx.x >> 5;
    const int lhi  = lane + 32;

    const float baLo = __ldg(ba + lane),  baHi = __ldg(ba + lhi);
    const float gnLo = __ldg(gng + lane), gnHi = __ldg(gng + lhi);
    const float gbLo = __ldg(gnb + lane), gbHi = __ldg(gnb + lhi);
    const float bfLo = __ldg(bf + lane),  bfHi = __ldg(bf + lhi);
    const float fgLo = __ldg(gfg + lane), fgHi = __ldg(gfg + lhi);
    const float fbLo = __ldg(gfb + lane), fbHi = __ldg(gfb + lhi);

    float* actw = sAct + warp * 512;
    const float4* waLo = reinterpret_cast<const float4*>(sWa + lane * 68);
    const float4* waHi = reinterpret_cast<const float4*>(sWa + lhi * 68);
    const float4* wfLo = reinterpret_cast<const float4*>(sWf + lane * 132);
    const float4* wfHi = reinterpret_cast<const float4*>(sWf + lhi * 132);

    const int nw = gridDim.x * 8;
    for (int n0 = (blockIdx.x * 8 + warp) * 4; n0 < N; n0 += nw * 4) {
        const unsigned msk = __ballot_sync(FULL, (lane < 4) && g_mask[n0 + lane]);
        if (msk == 0) {   // all 4 nodes untouched: copy through
            const float4* src = reinterpret_cast<const float4*>(gf + (size_t)n0 * 64);
            float4* dst = reinterpret_cast<float4*>(out + (size_t)n0 * 64);
            dst[lane] = src[lane];
            dst[lhi]  = src[lhi];
            continue;
        }
        const float s0v = (lane < 4) ? g_s0[n0 + lane] : 0.f;

        __syncwarp();
        float2 gfv[4];
        #pragma unroll
        for (int e = 0; e < 4; e++) {
            const float2 sv = *(reinterpret_cast<const float2*>(g_S) + (size_t)(n0 + e) * 32 + lane);
            reinterpret_cast<float2*>(actw + e * 128)[lane] = sv;
            gfv[e] = __ldg(reinterpret_cast<const float2*>(gf) + (size_t)(n0 + e) * 32 + lane);
        }
        __syncwarp();

        // phase 1: copy_pre = S @ Wa + s0*ba
        float2 aLo[4], aHi[4];
        #pragma unroll
        for (int e = 0; e < 4; e++) {
            const float s0e = __shfl_sync(FULL, s0v, e);
            aLo[e] = make_float2(s0e * baLo, 0.f);
            aHi[e] = make_float2(s0e * baHi, 0.f);
        }
        #pragma unroll
        for (int kq = 0; kq < 16; kq++) {
            const float4 wl = waLo[kq];
            const float4 wh = waHi[kq];
            #pragma unroll
            for (int e = 0; e < 4; e++) {
                const float4 h4 = *reinterpret_cast<const float4*>(actw + e * 128 + kq * 4);
                ffma2(aLo[e], h4.x, h4.y, wl.x, wl.y);
                ffma2(aLo[e], h4.z, h4.w, wl.z, wl.w);
                ffma2(aHi[e], h4.x, h4.y, wh.x, wh.y);
                ffma2(aHi[e], h4.z, h4.w, wh.z, wh.w);
            }
        }
        float cpLo[4], cpHi[4];
        #pragma unroll
        for (int e = 0; e < 4; e++) {
            const float yLo = aLo[e].x + aLo[e].y;
            const float yHi = aHi[e].x + aHi[e].y;
            float s = yLo + yHi;
            float q = fmaf(yLo, yLo, yHi * yHi);
            warp_reduce2(s, q);
            const float mean = s * 0.015625f;
            const float var  = fmaf(q, 0.015625f, -mean * mean);
            const float rs   = rsqrtf(var + 1e-5f);
            cpLo[e] = fmaf((yLo - mean) * rs, gnLo, gbLo);
            cpHi[e] = fmaf((yHi - mean) * rs, gnHi, gbHi);
        }

        __syncwarp();   // all lanes done reading S from actw
        #pragma unroll
        for (int e = 0; e < 4; e++) {
            reinterpret_cast<float2*>(actw + e * 128)[lane] = gfv[e];  // kk 0..63 = gf
            actw[e * 128 + 64 + lane] = cpLo[e];                        // kk 64..127 = copy
            actw[e * 128 + 96 + lane] = cpHi[e];
        }
        __syncwarp();

        // phase 2: fused = [gf, copy] @ Wf + bf
        #pragma unroll
        for (int e = 0; e < 4; e++) {
            aLo[e] = make_float2(bfLo, 0.f);
            aHi[e] = make_float2(bfHi, 0.f);
        }
        #pragma unroll
        for (int kq = 0; kq < 32; kq++) {
            const float4 wl = wfLo[kq];
            const float4 wh = wfHi[kq];
            #pragma unroll
            for (int e = 0; e < 4; e++) {
                const float4 h4 = *reinterpret_cast<const float4*>(actw + e * 128 + kq * 4);
                ffma2(aLo[e], h4.x, h4.y, wl.x, wl.y);
                ffma2(aLo[e], h4.z, h4.w, wl.z, wl.w);
                ffma2(aHi[e], h4.x, h4.y, wh.x, wh.y);
                ffma2(aHi[e], h4.z, h4.w, wh.z, wh.w);
            }
        }
        #pragma unroll
        for (int e = 0; e < 4; e++) {
            const float yLo = aLo[e].x + aLo[e].y;
            const float yHi = aHi[e].x + aHi[e].y;
            float s = yLo + yHi;
            float q = fmaf(yLo, yLo, yHi * yHi);
            warp_reduce2(s, q);
            const float mean = s * 0.015625f;
            const float var  = fmaf(q, 0.015625f, -mean * mean);
            const float rs   = rsqrtf(var + 1e-5f);
            float fLo = fmaf((yLo - mean) * rs, fgLo, fbLo);
            float fHi = fmaf((yHi - mean) * rs, fgHi, fbHi);
            fLo = fLo > 0.f ? fLo : 0.01f * fLo;
            fHi = fHi > 0.f ? fHi : 0.01f * fHi;
            if ((msk >> e) & 1) {
                out[(size_t)(n0 + e) * 64 + lane] = fLo;
                out[(size_t)(n0 + e) * 64 + lhi]  = fHi;
            } else {
                reinterpret_cast<float2*>(out)[(size_t)(n0 + e) * 32 + lane] = gfv[e];
            }
        }
    }
}

// ---------------------------------------------------------------------------
extern "C" void kernel_launch(void* const* d_in, const int* in_sizes, int n_in,
                              void* d_out, int out_size)
{
    const float* gf  = (const float*)d_in[0];
    const float* pos = (const float*)d_in[1];
    const int*   edg = (const int*)  d_in[2];
    const float* wgt = (const float*)d_in[3];
    const float* W1  = (const float*)d_in[4];
    const float* b1  = (const float*)d_in[5];
    const float* W2  = (const float*)d_in[6];
    const float* b2  = (const float*)d_in[7];
    const float* gdg = (const float*)d_in[8];
    const float* gdb = (const float*)d_in[9];
    const float* Wa  = (const float*)d_in[10];
    const float* ba  = (const float*)d_in[11];
    const float* gng = (const float*)d_in[12];
    const float* gnb = (const float*)d_in[13];
    const float* Wf  = (const float*)d_in[14];
    const float* bf  = (const float*)d_in[15];
    const float* gfg = (const float*)d_in[16];
    const float* gfb = (const float*)d_in[17];
    float* out = (float*)d_out;

    const int E = in_sizes[3];
    const int N = in_sizes[0] / 64;

    static const size_t node_smem = (4352 + 8448 + 4096) * sizeof(float);
    cudaFuncSetAttribute(node_kernel, cudaFuncAttributeMaxDynamicSharedMemorySize,
                         (int)node_smem);

    zero_kernel<<<1024, 256>>>(N);
    edge_kernel<<<444, 256>>>(gf, pos, edg, wgt, W1, b1, W2, b2, gdg, gdb, E);
    node_kernel<<<444, 256, node_smem>>>(gf, Wa, ba, gng, gnb, Wf, bf, gfg, gfb, out, N);
}

// round 4
// speedup vs baseline: 2.3921x; 1.0682x over previous
#include <cuda_runtime.h>

#define FULL 0xffffffffu

static constexpr int NMAX = 262144;   // 4*16*4096 nodes

// Scratch (allocation-free: device globals)
__device__ float         g_S[(size_t)NMAX * 64];
__device__ float         g_s0[NMAX];
__device__ unsigned char g_mask[NMAX];

// ---------------------------------------------------------------------------
// butterfly reduction of two values across the warp
__device__ __forceinline__ void warp_reduce2(float& s, float& q) {
    #pragma unroll
    for (int o = 16; o > 0; o >>= 1) {
        s += __shfl_xor_sync(FULL, s, o);
        q += __shfl_xor_sync(FULL, q, o);
    }
}

// packed f32x2 FMA: acc += {ax,ay} * {bx,by}
__device__ __forceinline__ void ffma2(float2& acc, float ax, float ay,
                                      float bx, float by) {
    float2 a = make_float2(ax, ay);
    float2 b = make_float2(bx, by);
    asm("fma.rn.f32x2 %0, %1, %2, %0;"
        : "+l"(reinterpret_cast<unsigned long long&>(acc))
        : "l"(reinterpret_cast<unsigned long long&>(a)),
          "l"(reinterpret_cast<unsigned long long&>(b)));
}

// ---------------------------------------------------------------------------
__global__ void __launch_bounds__(256) zero_kernel(int N) {
    const int stride = gridDim.x * blockDim.x;
    const int i = blockIdx.x * blockDim.x + threadIdx.x;
    const float4 z = make_float4(0.f, 0.f, 0.f, 0.f);
    const size_t total4 = (size_t)N * 16;
    for (size_t j = i; j < total4; j += stride)
        reinterpret_cast<float4*>(g_S)[j] = z;
    for (int j = i; j < N; j += stride) {
        g_s0[j] = 0.f;
        g_mask[j] = 0;
    }
}

// ---------------------------------------------------------------------------
// Edge kernel: warp processes 8 edges per iteration.
// Transposed W2 in smem (pitch 68), h staged in smem, f32x2 FMAs,
// gf gathers hoisted above the GEMV to hide latency.
// ---------------------------------------------------------------------------
__global__ void __launch_bounds__(256, 2) edge_kernel(
    const float* __restrict__ gf,
    const float* __restrict__ pos,
    const int*   __restrict__ edge,
    const float* __restrict__ wgt,
    const float* __restrict__ W1,
    const float* __restrict__ b1,
    const float* __restrict__ W2,
    const float* __restrict__ b2,
    const float* __restrict__ gdg,
    const float* __restrict__ gdb,
    int E)
{
    __shared__ float sW2t[64 * 68];     // W2t[c][k] = W2[k][c], pitch 68
    __shared__ float sht[8 * 8 * 64];   // h staging: [warp][edge][k]

    for (int i = threadIdx.x; i < 64 * 64; i += 256) {
        int k = i >> 6, c = i & 63;
        sW2t[c * 68 + k] = W2[i];
    }
    __syncthreads();

    const int lane = threadIdx.x & 31;
    const int warp = threadIdx.x >> 5;
    const int lhi  = lane + 32;

    // per-lane constants in registers (channels lane, lane+32)
    const float w1aLo = __ldg(W1 + lane),     w1bLo = __ldg(W1 + 64 + lane);
    const float w1aHi = __ldg(W1 + lhi),      w1bHi = __ldg(W1 + 64 + lhi);
    const float b1Lo  = __ldg(b1 + lane),     b1Hi  = __ldg(b1 + lhi);
    const float b2Lo  = __ldg(b2 + lane),     b2Hi  = __ldg(b2 + lhi);
    const float gLo   = __ldg(gdg + lane),    gHi   = __ldg(gdg + lhi);
    const float btLo  = __ldg(gdb + lane),    btHi  = __ldg(gdb + lhi);

    float* hme = sht + warp * 512;
    const float4* wrLo = reinterpret_cast<const float4*>(sW2t + lane * 68);
    const float4* wrHi = reinterpret_cast<const float4*>(sW2t + lhi * 68);

    const int nw = gridDim.x * 8;
    for (int e0 = (blockIdx.x * 8 + warp) * 8; e0 < E; e0 += nw * 8) {
        int pre = 0, suc = 0;
        float pd0 = 0.f, pd1 = 0.f, w = 0.f;
        if (lane < 8) {
            const int ei = min(e0 + lane, E - 1);
            const int4 ed = __ldg(reinterpret_cast<const int4*>(edge) + ei);
            pre = (ed.x * 16 + ed.y) * 4096 + ed.z;
            suc = pre - ed.z + 4096 + ed.w;
            const float2 P0 = __ldg(reinterpret_cast<const float2*>(pos) + ed.y * 4096 + ed.z);
            const float2 P1 = __ldg(reinterpret_cast<const float2*>(pos) + (ed.y + 1) * 4096 + ed.w);
            pd0 = P1.x - P0.x;
            pd1 = P1.y - P0.y;
            w = __ldg(wgt + ei);
        }
        __syncwarp();

        // hoist gathers: issue all 16 LDG now, consume after the GEMV
        float vLo[8], vHi[8];
        #pragma unroll
        for (int e = 0; e < 8; e++) {
            const int preE = __shfl_sync(FULL, pre, e);
            vLo[e] = __ldg(gf + (size_t)preE * 64 + lane);
            vHi[e] = __ldg(gf + (size_t)preE * 64 + lhi);
        }

        // compute + stage h for 8 edges (natural k order)
        #pragma unroll
        for (int e = 0; e < 8; e++) {
            const float p0 = __shfl_sync(FULL, pd0, e);
            const float p1 = __shfl_sync(FULL, pd1, e);
            const float za = fmaf(p1, w1bLo, fmaf(p0, w1aLo, b1Lo));
            const float zb = fmaf(p1, w1bHi, fmaf(p0, w1aHi, b1Hi));
            hme[e * 64 + lane] = za > 0.f ? za : 0.01f * za;
            hme[e * 64 + lhi]  = zb > 0.f ? zb : 0.01f * zb;
        }
        __syncwarp();

        float2 aLo[8], aHi[8];
        #pragma unroll
        for (int e = 0; e < 8; e++) {
            aLo[e] = make_float2(b2Lo, 0.f);
            aHi[e] = make_float2(b2Hi, 0.f);
        }
        #pragma unroll
        for (int kq = 0; kq < 16; kq++) {
            const float4 wl = wrLo[kq];
            const float4 wh = wrHi[kq];
            #pragma unroll
            for (int e = 0; e < 8; e++) {
                const float4 h4 = *reinterpret_cast<const float4*>(hme + e * 64 + kq * 4);
                ffma2(aLo[e], h4.x, h4.y, wl.x, wl.y);
                ffma2(aLo[e], h4.z, h4.w, wl.z, wl.w);
                ffma2(aHi[e], h4.x, h4.y, wh.x, wh.y);
                ffma2(aHi[e], h4.z, h4.w, wh.z, wh.w);
            }
        }

        #pragma unroll
        for (int e = 0; e < 8; e++) {
            const float yLo = aLo[e].x + aLo[e].y;
            const float yHi = aHi[e].x + aHi[e].y;
            float s = yLo + yHi;
            float q = fmaf(yLo, yLo, yHi * yHi);
            warp_reduce2(s, q);
            const float mean = s * 0.015625f;
            const float var  = fmaf(q, 0.015625f, -mean * mean);
            const float rs   = rsqrtf(var + 1e-5f);
            const float dLo = fmaf((yLo - mean) * rs, gLo, btLo);
            const float dHi = fmaf((yHi - mean) * rs, gHi, btHi);

            const int   sucE = __shfl_sync(FULL, suc, e);
            const float wE   = __shfl_sync(FULL, w, e);

            const float ox = wE * (vLo[e] + dLo);
            const float oy = wE * (vHi[e] + dHi);

            // regroup for vectorized reductions
            const float a1 = __shfl_down_sync(FULL, ox, 1);
            const float a2 = __shfl_down_sync(FULL, ox, 2);
            const float a3 = __shfl_down_sync(FULL, ox, 3);
            const float u2 = __shfl_up_sync(FULL, oy, 2);
            const float u1 = __shfl_up_sync(FULL, oy, 1);
            const float d1 = __shfl_down_sync(FULL, oy, 1);

            if (e0 + e < E) {
                if ((lane & 3) == 0) {
                    float* adr = g_S + (size_t)sucE * 64 + lane;   // channels lane..lane+3
                    asm volatile("red.global.add.v4.f32 [%0], {%1,%2,%3,%4};"
                                 :: "l"(adr), "f"(ox), "f"(a1), "f"(a2), "f"(a3) : "memory");
                }
                if ((lane & 3) == 2) {
                    float* adr = g_S + (size_t)sucE * 64 + 30 + lane; // channels 32+(lane-2)..
                    asm volatile("red.global.add.v4.f32 [%0], {%1,%2,%3,%4};"
                                 :: "l"(adr), "f"(u2), "f"(u1), "f"(oy), "f"(d1) : "memory");
                }
                if (lane == 0) {
                    atomicAdd(g_s0 + sucE, wE);
                    g_mask[sucE] = 1;
                }
            }
        }
    }
}

// ---------------------------------------------------------------------------
// Node kernel: warp processes 8 nodes per iteration. Dynamic smem:
// Wa^T (pitch 68) + Wf^T (pitch 132) + activation staging [warp][node][128].
// ---------------------------------------------------------------------------
__global__ void __launch_bounds__(256, 2) node_kernel(
    const float* __restrict__ gf,
    const float* __restrict__ Wa,
    const float* __restrict__ ba,
    const float* __restrict__ gng,
    const float* __restrict__ gnb,
    const float* __restrict__ Wf,
    const float* __restrict__ bf,
    const float* __restrict__ gfg,
    const float* __restrict__ gfb,
    float* __restrict__ out,
    int N)
{
    extern __shared__ float sm[];
    float* sWa  = sm;                    // 64*68  = 4352 floats
    float* sWf  = sm + 4352;             // 64*132 = 8448 floats
    float* sAct = sm + 4352 + 8448;      // 8 warps * 8 nodes * 128 = 8192 floats

    for (int i = threadIdx.x; i < 64 * 64; i += 256) {
        int k = i >> 6, c = i & 63;
        sWa[c * 68 + k] = Wa[i];
    }
    for (int i = threadIdx.x; i < 128 * 64; i += 256) {
        int k = i >> 6, c = i & 63;
        sWf[c * 132 + k] = Wf[i];
    }
    __syncthreads();

    const int lane = threadIdx.x & 31;
    const int warp = threadIdx.x >> 5;
    const int lhi  = lane + 32;

    const float baLo = __ldg(ba + lane),  baHi = __ldg(ba + lhi);
    const float gnLo = __ldg(gng + lane), gnHi = __ldg(gng + lhi);
    const float gbLo = __ldg(gnb + lane), gbHi = __ldg(gnb + lhi);
    const float bfLo = __ldg(bf + lane),  bfHi = __ldg(bf + lhi);
    const float fgLo = __ldg(gfg + lane), fgHi = __ldg(gfg + lhi);
    const float fbLo = __ldg(gfb + lane), fbHi = __ldg(gfb + lhi);

    float* actw = sAct + warp * 1024;
    const float4* waLo = reinterpret_cast<const float4*>(sWa + lane * 68);
    const float4* waHi = reinterpret_cast<const float4*>(sWa + lhi * 68);
    const float4* wfLo = reinterpret_cast<const float4*>(sWf + lane * 132);
    const float4* wfHi = reinterpret_cast<const float4*>(sWf + lhi * 132);

    const int nw = gridDim.x * 8;
    for (int n0 = (blockIdx.x * 8 + warp) * 8; n0 < N; n0 += nw * 8) {
        const unsigned msk = __ballot_sync(FULL, (lane < 8) && g_mask[n0 + lane]);
        if (msk == 0) {   // all 8 nodes untouched: copy through
            const float4* src = reinterpret_cast<const float4*>(gf + (size_t)n0 * 64);
            float4* dst = reinterpret_cast<float4*>(out + (size_t)n0 * 64);
            #pragma unroll
            for (int j = 0; j < 4; j++)
                dst[j * 32 + lane] = src[j * 32 + lane];
            continue;
        }
        const float s0v = (lane < 8) ? g_s0[n0 + lane] : 0.f;

        __syncwarp();
        float2 gfv[8];
        #pragma unroll
        for (int e = 0; e < 8; e++) {
            const float2 sv = *(reinterpret_cast<const float2*>(g_S) + (size_t)(n0 + e) * 32 + lane);
            reinterpret_cast<float2*>(actw + e * 128)[lane] = sv;
            gfv[e] = __ldg(reinterpret_cast<const float2*>(gf) + (size_t)(n0 + e) * 32 + lane);
        }
        __syncwarp();

        // phase 1: copy_pre = S @ Wa + s0*ba
        float2 aLo[8], aHi[8];
        #pragma unroll
        for (int e = 0; e < 8; e++) {
            const float s0e = __shfl_sync(FULL, s0v, e);
            aLo[e] = make_float2(s0e * baLo, 0.f);
            aHi[e] = make_float2(s0e * baHi, 0.f);
        }
        #pragma unroll
        for (int kq = 0; kq < 16; kq++) {
            const float4 wl = waLo[kq];
            const float4 wh = waHi[kq];
            #pragma unroll
            for (int e = 0; e < 8; e++) {
                const float4 h4 = *reinterpret_cast<const float4*>(actw + e * 128 + kq * 4);
                ffma2(aLo[e], h4.x, h4.y, wl.x, wl.y);
                ffma2(aLo[e], h4.z, h4.w, wl.z, wl.w);
                ffma2(aHi[e], h4.x, h4.y, wh.x, wh.y);
                ffma2(aHi[e], h4.z, h4.w, wh.z, wh.w);
            }
        }
        float cpLo[8], cpHi[8];
        #pragma unroll
        for (int e = 0; e < 8; e++) {
            const float yLo = aLo[e].x + aLo[e].y;
            const float yHi = aHi[e].x + aHi[e].y;
            float s = yLo + yHi;
            float q = fmaf(yLo, yLo, yHi * yHi);
            warp_reduce2(s, q);
            const float mean = s * 0.015625f;
            const float var  = fmaf(q, 0.015625f, -mean * mean);
            const float rs   = rsqrtf(var + 1e-5f);
            cpLo[e] = fmaf((yLo - mean) * rs, gnLo, gbLo);
            cpHi[e] = fmaf((yHi - mean) * rs, gnHi, gbHi);
        }

        __syncwarp();   // all lanes done reading S from actw
        #pragma unroll
        for (int e = 0; e < 8; e++) {
            reinterpret_cast<float2*>(actw + e * 128)[lane] = gfv[e];  // kk 0..63 = gf
            actw[e * 128 + 64 + lane] = cpLo[e];                        // kk 64..127 = copy
            actw[e * 128 + 96 + lane] = cpHi[e];
        }
        __syncwarp();

        // phase 2: fused = [gf, copy] @ Wf + bf
        #pragma unroll
        for (int e = 0; e < 8; e++) {
            aLo[e] = make_float2(bfLo, 0.f);
            aHi[e] = make_float2(bfHi, 0.f);
        }
        #pragma unroll
        for (int kq = 0; kq < 32; kq++) {
            const float4 wl = wfLo[kq];
            const float4 wh = wfHi[kq];
            #pragma unroll
            for (int e = 0; e < 8; e++) {
                const float4 h4 = *reinterpret_cast<const float4*>(actw + e * 128 + kq * 4);
                ffma2(aLo[e], h4.x, h4.y, wl.x, wl.y);
                ffma2(aLo[e], h4.z, h4.w, wl.z, wl.w);
                ffma2(aHi[e], h4.x, h4.y, wh.x, wh.y);
                ffma2(aHi[e], h4.z, h4.w, wh.z, wh.w);
            }
        }
        #pragma unroll
        for (int e = 0; e < 8; e++) {
            const float yLo = aLo[e].x + aLo[e].y;
            const float yHi = aHi[e].x + aHi[e].y;
            float s = yLo + yHi;
            float q = fmaf(yLo, yLo, yHi * yHi);
            warp_reduce2(s, q);
            const float mean = s * 0.015625f;
            const float var  = fmaf(q, 0.015625f, -mean * mean);
            const float rs   = rsqrtf(var + 1e-5f);
            float fLo = fmaf((yLo - mean) * rs, fgLo, fbLo);
            float fHi = fmaf((yHi - mean) * rs, fgHi, fbHi);
            fLo = fLo > 0.f ? fLo : 0.01f * fLo;
            fHi = fHi > 0.f ? fHi : 0.01f * fHi;
            if ((msk >> e) & 1) {
                out[(size_t)(n0 + e) * 64 + lane] = fLo;
                out[(size_t)(n0 + e) * 64 + lhi]  = fHi;
            } else {
                reinterpret_cast<float2*>(out)[(size_t)(n0 + e) * 32 + lane] = gfv[e];
            }
        }
    }
}

// ---------------------------------------------------------------------------
extern "C" void kernel_launch(void* const* d_in, const int* in_sizes, int n_in,
                              void* d_out, int out_size)
{
    const float* gf  = (const float*)d_in[0];
    const float* pos = (const float*)d_in[1];
    const int*   edg = (const int*)  d_in[2];
    const float* wgt = (const float*)d_in[3];
    const float* W1  = (const float*)d_in[4];
    const float* b1  = (const float*)d_in[5];
    const float* W2  = (const float*)d_in[6];
    const float* b2  = (const float*)d_in[7];
    const float* gdg = (const float*)d_in[8];
    const float* gdb = (const float*)d_in[9];
    const float* Wa  = (const float*)d_in[10];
    const float* ba  = (const float*)d_in[11];
    const float* gng = (const float*)d_in[12];
    const float* gnb = (const float*)d_in[13];
    const float* Wf  = (const float*)d_in[14];
    const float* bf  = (const float*)d_in[15];
    const float* gfg = (const float*)d_in[16];
    const float* gfb = (const float*)d_in[17];
    float* out = (float*)d_out;

    const int E = in_sizes[3];
    const int N = in_sizes[0] / 64;

    static const size_t node_smem = (4352 + 8448 + 8192) * sizeof(float);
    cudaFuncSetAttribute(node_kernel, cudaFuncAttributeMaxDynamicSharedMemorySize,
                         (int)node_smem);

    zero_kernel<<<2368, 256>>>(N);
    edge_kernel<<<296, 256>>>(gf, pos, edg, wgt, W1, b1, W2, b2, gdg, gdb, E);
    node_kernel<<<296, 256, node_smem>>>(gf, Wa, ba, gng, gnb, Wf, bf, gfg, gfb, out, N);
}